// round 10
// baseline (speedup 1.0000x reference)
#include <cuda_runtime.h>
#include <cuda_bf16.h>
#include <cstdint>

// Problem constants (fixed by the reference: S=64, C=32)
#define SPATIAL 64
#define KEY_SPACE (SPATIAL * SPATIAL * SPATIAL * SPATIAL)  // 16,777,216
#define NWORDS (KEY_SPACE / 32)                            // 524,288
#define NBLOCKS_SCAN 512                                   // NWORDS / 1024
#define MAXN (1 << 21)

// Scratch (device globals — zero at module load; every call restores zeros,
// so every graph replay observes identical initial state).
__device__ unsigned g_bitmap[NWORDS];      // presence bits (restored by scan)
__device__ unsigned g_dup[NWORDS];         // dup bits      (restored by scan)
__device__ uint4    g_packed[NWORDS];      // {present, dup, prefix, 0} for scatter
__device__ unsigned long long g_scanState[NBLOCKS_SCAN];  // zeroed by build
__device__ unsigned g_keys[MAXN];
__device__ unsigned g_numUnique;

// ---------------------------------------------------------------------------
// 1) presence + dup bitmaps, key cache — 4 points/thread, 4 INDEPENDENT chains
//    (scalar key stores; no register coupling between the four points).
__global__ void k_build(const int4* __restrict__ coords, int n) {
    int tid = blockIdx.x * blockDim.x + threadIdx.x;
    if (tid < NBLOCKS_SCAN) g_scanState[tid] = 0ULL;  // consumed only by next launch
    int i0 = tid * 4;
    if (i0 >= n) return;

    // front-batch 4 independent coordinate loads (64B contiguous)
    int4 c[4];
#pragma unroll
    for (int j = 0; j < 4; j++)
        if (i0 + j < n) c[j] = coords[i0 + j];

    // 4 independent key computations + scalar stores (fire-and-forget,
    // each depends only on its own load)
    unsigned key[4];
#pragma unroll
    for (int j = 0; j < 4; j++) {
        if (i0 + j < n) {
            key[j] = ((unsigned)((c[j].x * SPATIAL + c[j].y) * SPATIAL + c[j].z)) * SPATIAL
                     + (unsigned)c[j].w;
            g_keys[i0 + j] = key[j];
        }
    }

    // 4 independent atomic chains (each: ATOMG.return -> predicated dup ATOMG)
#pragma unroll
    for (int j = 0; j < 4; j++) {
        if (i0 + j < n) {
            unsigned bit = 1u << (key[j] & 31);
            unsigned old = atomicOr(&g_bitmap[key[j] >> 5], bit);
            if (old & bit) atomicOr(&g_dup[key[j] >> 5], bit);
        }
    }
}

// ---------------------------------------------------------------------------
// 2) single-pass scan (decoupled lookback) -> packed table + dup-row zeroing.
//    Restores g_bitmap / g_dup to zero for the next replay. (R9-proven)
__global__ void __launch_bounds__(256) k_scan_fused(float4* __restrict__ out) {
    int blk = blockIdx.x, t = threadIdx.x;
    int gw4 = blk * 256 + t;
    uint4 v  = ((const uint4*)g_bitmap)[gw4];
    uint4 d4 = ((const uint4*)g_dup)[gw4];
    unsigned c0 = __popc(v.x), c1 = __popc(v.y), c2 = __popc(v.z), c3 = __popc(v.w);
    unsigned local = c0 + c1 + c2 + c3;

    // restore zeros (scatter reads only g_packed / g_keys)
    uint4 z4 = make_uint4(0, 0, 0, 0);
    ((uint4*)g_bitmap)[gw4] = z4;
    ((uint4*)g_dup)[gw4] = z4;

    // intra-warp inclusive scan
    unsigned inc = local;
#pragma unroll
    for (int o = 1; o < 32; o <<= 1) {
        unsigned nv = __shfl_up_sync(0xffffffffu, inc, o);
        if ((t & 31) >= o) inc += nv;
    }
    __shared__ unsigned ws[8];
    __shared__ unsigned sh_total, sh_excl;
    if ((t & 31) == 31) ws[t >> 5] = inc;
    __syncthreads();
    if (t < 8) {
        unsigned x = ws[t], xi = x;
#pragma unroll
        for (int o = 1; o < 8; o <<= 1) {
            unsigned nv = __shfl_up_sync(0xffu, xi, o);
            if (t >= o) xi += nv;
        }
        ws[t] = xi - x;
        if (t == 7) sh_total = xi;
    }
    __syncthreads();
    unsigned blockTotal = sh_total;

    // publish partial, then decoupled lookback (warp 0)
    if (t == 0)
        atomicExch(&g_scanState[blk], ((unsigned long long)blockTotal << 32) | 1ULL);
    if (t < 32) {
        unsigned excl = 0;
        int idx = blk - 1;
        while (idx >= 0) {
            int look = idx - t;
            unsigned long long s;
            unsigned flag;
            do {
                s = (look >= 0) ? *(volatile unsigned long long*)&g_scanState[look]
                                : 3ULL;
                flag = (unsigned)s;
            } while (__any_sync(0xffffffffu, flag == 0));
            unsigned val = (unsigned)(s >> 32);
            unsigned inclMask = __ballot_sync(0xffffffffu, look >= 0 && flag == 2);
            unsigned contrib;
            if (inclMask) {
                int fi = __ffs(inclMask) - 1;
                contrib = (t <= (unsigned)fi && look >= 0) ? val : 0;
            } else {
                contrib = (look >= 0) ? val : 0;
            }
#pragma unroll
            for (int o = 16; o; o >>= 1) contrib += __shfl_down_sync(0xffffffffu, contrib, o);
            excl += __shfl_sync(0xffffffffu, contrib, 0);
            if (inclMask) break;
            idx -= 32;
        }
        if (t == 0) {
            atomicExch(&g_scanState[blk],
                       ((unsigned long long)(excl + blockTotal) << 32) | 2ULL);
            sh_excl = excl;
            if (blk == NBLOCKS_SCAN - 1) g_numUnique = excl + blockTotal;
        }
    }
    __syncthreads();

    unsigned base = sh_excl + ws[t >> 5] + (inc - local);
    unsigned pw[4] = {v.x, v.y, v.z, v.w};
    unsigned dw[4] = {d4.x, d4.y, d4.z, d4.w};
    unsigned bw[4];
    bw[0] = base;
    bw[1] = base + c0;
    bw[2] = bw[1] + c1;
    bw[3] = bw[2] + c2;
    float4 z = make_float4(0.f, 0.f, 0.f, 0.f);
#pragma unroll
    for (int k = 0; k < 4; k++) {
        g_packed[gw4 * 4 + k] = make_uint4(pw[k], dw[k], bw[k], 0u);
        unsigned d = dw[k];
        while (d) {
            int b = __ffs(d) - 1;
            d &= d - 1;
            unsigned rank = bw[k] + __popc(pw[k] & ((1u << b) - 1u));
            float4* dst = out + (size_t)rank * 8;
#pragma unroll
            for (int q = 0; q < 8; q++) dst[q] = z;
        }
    }
}

// ---------------------------------------------------------------------------
// 3) scatter: 4 threads/point, 2 float4 each; packed-table lookup; pad zero
//    (R9-proven)
__global__ void k_scatter(const float4* __restrict__ feat,
                          float4* __restrict__ out, int n) {
    int tid = blockIdx.x * blockDim.x + threadIdx.x;
    int p = tid >> 2;    // point index
    int sub = tid & 3;   // handles quarter-rows sub and sub+4
    if (p >= n) return;
    int lane = threadIdx.x & 31;
    unsigned info = 0;
    if (sub == 0) {
        unsigned key = g_keys[p];
        uint4 pk = g_packed[key >> 5];      // single 16B L2 lookup
        unsigned b = key & 31;
        unsigned rank = pk.z + __popc(pk.x & ((1u << b) - 1u));
        unsigned isdup = (pk.y >> b) & 1u;
        info = rank | (isdup << 31);
    }
    info = __shfl_sync(0xffffffffu, info, lane & ~3);
    unsigned rank = info & 0x7fffffffu;
    float4 f0 = feat[p * 8 + sub];
    float4 f1 = feat[p * 8 + sub + 4];
    float4* dst = out + (size_t)rank * 8;
    if (info >> 31) {
        asm volatile("red.global.add.v4.f32 [%0], {%1,%2,%3,%4};"
                     :: "l"((float*)(dst + sub)), "f"(f0.x), "f"(f0.y), "f"(f0.z), "f"(f0.w)
                     : "memory");
        asm volatile("red.global.add.v4.f32 [%0], {%1,%2,%3,%4};"
                     :: "l"((float*)(dst + sub + 4)), "f"(f1.x), "f"(f1.y), "f"(f1.z), "f"(f1.w)
                     : "memory");
    } else {
        dst[sub] = f0;
        dst[sub + 4] = f1;
    }

    // padding rows [numUnique, n): never touched by scatter, safe to zero here
    unsigned nu = g_numUnique;
    unsigned row = nu + (unsigned)p;
    if (row < (unsigned)n) {
        float4 z = make_float4(0.f, 0.f, 0.f, 0.f);
        out[(size_t)row * 8 + sub] = z;
        out[(size_t)row * 8 + sub + 4] = z;
    }
}

// ---------------------------------------------------------------------------
extern "C" void kernel_launch(void* const* d_in, const int* in_sizes, int n_in,
                              void* d_out, int out_size) {
    const int4*   coords = (const int4*)d_in[0];
    const float4* feat   = (const float4*)d_in[1];
    float4*       out    = (float4*)d_out;
    int n = in_sizes[0] / 4;

    int buildThreads = (n + 3) / 4;
    k_build<<<(buildThreads + 255) / 256, 256>>>(coords, n);
    k_scan_fused<<<NBLOCKS_SCAN, 256>>>(out);
    k_scatter<<<(n * 4 + 255) / 256, 256>>>(feat, out, n);
}

// round 11
// speedup vs baseline: 1.0511x; 1.0511x over previous
#include <cuda_runtime.h>
#include <cuda_bf16.h>
#include <cstdint>

// Problem constants (fixed by the reference: S=64, C=32)
#define SPATIAL 64
#define KEY_SPACE (SPATIAL * SPATIAL * SPATIAL * SPATIAL)  // 16,777,216
#define NWORDS (KEY_SPACE / 32)                            // 524,288
#define NBLOCKS_SCAN 512                                   // NWORDS / 1024
#define MAXN (1 << 21)

// Programmatic dependent launch controls
#define GDC_WAIT()   asm volatile("griddepcontrol.wait;" ::: "memory")
#define GDC_LAUNCH() asm volatile("griddepcontrol.launch_dependents;" :::)

// Scratch (device globals — zero at module load; every call restores zeros,
// so every graph replay observes identical initial state).
__device__ unsigned g_bitmap[NWORDS];      // presence bits (restored by scan)
__device__ unsigned g_dup[NWORDS];         // dup bits      (restored by scan)
__device__ uint4    g_packed[NWORDS];      // {present, dup, prefix, 0} for scatter
__device__ unsigned long long g_scanState[NBLOCKS_SCAN];  // zeroed by build
__device__ unsigned g_keys[MAXN];
__device__ unsigned g_numUnique;

// ---------------------------------------------------------------------------
// 1) presence + dup bitmaps, key cache — 1 point/thread (best measured)
__global__ void k_build(const int4* __restrict__ coords, int n) {
    int i = blockIdx.x * blockDim.x + threadIdx.x;
    if (i < NBLOCKS_SCAN) g_scanState[i] = 0ULL;  // consumed only by next launch
    if (i >= n) return;
    int4 c = coords[i];
    unsigned key = ((unsigned)((c.x * SPATIAL + c.y) * SPATIAL + c.z)) * SPATIAL + (unsigned)c.w;
    g_keys[i] = key;
    unsigned bit = 1u << (key & 31);
    unsigned old = atomicOr(&g_bitmap[key >> 5], bit);
    if (old & bit) atomicOr(&g_dup[key >> 5], bit);
}

// ---------------------------------------------------------------------------
// 2) single-pass scan (decoupled lookback) -> packed table + dup-row zeroing.
//    Restores g_bitmap / g_dup to zero for the next replay.
//    PDL: waits for build; releases scatter immediately (scatter's pre-wait
//    section touches only inputs).
__global__ void __launch_bounds__(256) k_scan_fused(float4* __restrict__ out) {
    GDC_LAUNCH();   // let scatter's first wave come up while we run
    GDC_WAIT();     // build's writes must be visible before reading bitmaps

    int blk = blockIdx.x, t = threadIdx.x;
    int gw4 = blk * 256 + t;
    uint4 v  = ((const uint4*)g_bitmap)[gw4];
    uint4 d4 = ((const uint4*)g_dup)[gw4];
    unsigned c0 = __popc(v.x), c1 = __popc(v.y), c2 = __popc(v.z), c3 = __popc(v.w);
    unsigned local = c0 + c1 + c2 + c3;

    // restore zeros (scatter reads only g_packed / g_keys)
    uint4 z4 = make_uint4(0, 0, 0, 0);
    ((uint4*)g_bitmap)[gw4] = z4;
    ((uint4*)g_dup)[gw4] = z4;

    // intra-warp inclusive scan
    unsigned inc = local;
#pragma unroll
    for (int o = 1; o < 32; o <<= 1) {
        unsigned nv = __shfl_up_sync(0xffffffffu, inc, o);
        if ((t & 31) >= o) inc += nv;
    }
    __shared__ unsigned ws[8];
    __shared__ unsigned sh_total, sh_excl;
    if ((t & 31) == 31) ws[t >> 5] = inc;
    __syncthreads();
    if (t < 8) {
        unsigned x = ws[t], xi = x;
#pragma unroll
        for (int o = 1; o < 8; o <<= 1) {
            unsigned nv = __shfl_up_sync(0xffu, xi, o);
            if (t >= o) xi += nv;
        }
        ws[t] = xi - x;
        if (t == 7) sh_total = xi;
    }
    __syncthreads();
    unsigned blockTotal = sh_total;

    // publish partial, then decoupled lookback (warp 0)
    if (t == 0)
        atomicExch(&g_scanState[blk], ((unsigned long long)blockTotal << 32) | 1ULL);
    if (t < 32) {
        unsigned excl = 0;
        int idx = blk - 1;
        while (idx >= 0) {
            int look = idx - t;
            unsigned long long s;
            unsigned flag;
            do {
                s = (look >= 0) ? *(volatile unsigned long long*)&g_scanState[look]
                                : 3ULL;
                flag = (unsigned)s;
            } while (__any_sync(0xffffffffu, flag == 0));
            unsigned val = (unsigned)(s >> 32);
            unsigned inclMask = __ballot_sync(0xffffffffu, look >= 0 && flag == 2);
            unsigned contrib;
            if (inclMask) {
                int fi = __ffs(inclMask) - 1;
                contrib = (t <= (unsigned)fi && look >= 0) ? val : 0;
            } else {
                contrib = (look >= 0) ? val : 0;
            }
#pragma unroll
            for (int o = 16; o; o >>= 1) contrib += __shfl_down_sync(0xffffffffu, contrib, o);
            excl += __shfl_sync(0xffffffffu, contrib, 0);
            if (inclMask) break;
            idx -= 32;
        }
        if (t == 0) {
            atomicExch(&g_scanState[blk],
                       ((unsigned long long)(excl + blockTotal) << 32) | 2ULL);
            sh_excl = excl;
            if (blk == NBLOCKS_SCAN - 1) g_numUnique = excl + blockTotal;
        }
    }
    __syncthreads();

    unsigned base = sh_excl + ws[t >> 5] + (inc - local);
    unsigned pw[4] = {v.x, v.y, v.z, v.w};
    unsigned dw[4] = {d4.x, d4.y, d4.z, d4.w};
    unsigned bw[4];
    bw[0] = base;
    bw[1] = base + c0;
    bw[2] = bw[1] + c1;
    bw[3] = bw[2] + c2;
    float4 z = make_float4(0.f, 0.f, 0.f, 0.f);
#pragma unroll
    for (int k = 0; k < 4; k++) {
        g_packed[gw4 * 4 + k] = make_uint4(pw[k], dw[k], bw[k], 0u);
        unsigned d = dw[k];
        while (d) {
            int b = __ffs(d) - 1;
            d &= d - 1;
            unsigned rank = bw[k] + __popc(pw[k] & ((1u << b) - 1u));
            float4* dst = out + (size_t)rank * 8;
#pragma unroll
            for (int q = 0; q < 8; q++) dst[q] = z;
        }
    }
}

// ---------------------------------------------------------------------------
// 3) scatter: 4 threads/point, 2 float4 each; packed-table lookup; pad zero.
//    PDL: feat loads (pure input) issue BEFORE the wait and overlap with scan.
__global__ void k_scatter(const float4* __restrict__ feat,
                          float4* __restrict__ out, int n) {
    int tid = blockIdx.x * blockDim.x + threadIdx.x;
    int p = tid >> 2;    // point index
    int sub = tid & 3;   // handles quarter-rows sub and sub+4
    float4 f0, f1;
    if (p < n) {
        f0 = feat[p * 8 + sub];       // independent of build/scan — prefetch
        f1 = feat[p * 8 + sub + 4];
    }
    GDC_WAIT();                       // scan (and transitively build) complete
    if (p >= n) return;

    int lane = threadIdx.x & 31;
    unsigned info = 0;
    if (sub == 0) {
        unsigned key = g_keys[p];
        uint4 pk = g_packed[key >> 5];      // single 16B L2 lookup
        unsigned b = key & 31;
        unsigned rank = pk.z + __popc(pk.x & ((1u << b) - 1u));
        unsigned isdup = (pk.y >> b) & 1u;
        info = rank | (isdup << 31);
    }
    info = __shfl_sync(0xffffffffu, info, lane & ~3);
    unsigned rank = info & 0x7fffffffu;
    float4* dst = out + (size_t)rank * 8;
    if (info >> 31) {
        asm volatile("red.global.add.v4.f32 [%0], {%1,%2,%3,%4};"
                     :: "l"((float*)(dst + sub)), "f"(f0.x), "f"(f0.y), "f"(f0.z), "f"(f0.w)
                     : "memory");
        asm volatile("red.global.add.v4.f32 [%0], {%1,%2,%3,%4};"
                     :: "l"((float*)(dst + sub + 4)), "f"(f1.x), "f"(f1.y), "f"(f1.z), "f"(f1.w)
                     : "memory");
    } else {
        dst[sub] = f0;
        dst[sub + 4] = f1;
    }

    // padding rows [numUnique, n): never touched by scatter, safe to zero here
    unsigned nu = g_numUnique;
    unsigned row = nu + (unsigned)p;
    if (row < (unsigned)n) {
        float4 z = make_float4(0.f, 0.f, 0.f, 0.f);
        out[(size_t)row * 8 + sub] = z;
        out[(size_t)row * 8 + sub + 4] = z;
    }
}

// ---------------------------------------------------------------------------
extern "C" void kernel_launch(void* const* d_in, const int* in_sizes, int n_in,
                              void* d_out, int out_size) {
    const int4*   coords = (const int4*)d_in[0];
    const float4* feat   = (const float4*)d_in[1];
    float4*       out    = (float4*)d_out;
    int n = in_sizes[0] / 4;

    // 1) build — plain launch
    k_build<<<(n + 255) / 256, 256>>>(coords, n);

    // 2) scan — programmatic dependent launch (overlaps build's drain)
    {
        cudaLaunchConfig_t cfg = {};
        cfg.gridDim = dim3(NBLOCKS_SCAN, 1, 1);
        cfg.blockDim = dim3(256, 1, 1);
        cudaLaunchAttribute attr[1];
        attr[0].id = cudaLaunchAttributeProgrammaticStreamSerialization;
        attr[0].val.programmaticStreamSerializationAllowed = 1;
        cfg.attrs = attr;
        cfg.numAttrs = 1;
        cudaLaunchKernelEx(&cfg, k_scan_fused, out);
    }

    // 3) scatter — programmatic dependent launch (feat prefetch overlaps scan)
    {
        int total = n * 4;
        cudaLaunchConfig_t cfg = {};
        cfg.gridDim = dim3((total + 255) / 256, 1, 1);
        cfg.blockDim = dim3(256, 1, 1);
        cudaLaunchAttribute attr[1];
        attr[0].id = cudaLaunchAttributeProgrammaticStreamSerialization;
        attr[0].val.programmaticStreamSerializationAllowed = 1;
        cfg.attrs = attr;
        cfg.numAttrs = 1;
        cudaLaunchKernelEx(&cfg, k_scatter, feat, out, n);
    }
}

// round 12
// speedup vs baseline: 1.0545x; 1.0033x over previous
#include <cuda_runtime.h>
#include <cuda_bf16.h>
#include <cstdint>

// Problem constants (fixed by the reference: S=64, C=32)
#define SPATIAL 64
#define KEY_SPACE (SPATIAL * SPATIAL * SPATIAL * SPATIAL)  // 16,777,216
#define NWORDS (KEY_SPACE / 32)                            // 524,288
#define NBLOCKS_SCAN 512                                   // NWORDS / 1024
#define MAXN (1 << 21)

// Programmatic dependent launch controls
#define GDC_WAIT()   asm volatile("griddepcontrol.wait;" ::: "memory")
#define GDC_LAUNCH() asm volatile("griddepcontrol.launch_dependents;" :::)

// Scratch (device globals — zero at module load; every call restores zeros,
// so every graph replay observes identical initial state).
__device__ unsigned g_bitmap[NWORDS];      // presence bits (restored by scan)
__device__ unsigned g_dup[NWORDS];         // dup bits      (restored by scan)
__device__ uint4    g_packed[NWORDS];      // {present, dup, prefix, 0} for scatter
__device__ unsigned long long g_scanState[NBLOCKS_SCAN];  // zeroed by build
__device__ unsigned g_keys[MAXN];
__device__ unsigned g_numUnique;

// ---------------------------------------------------------------------------
// 1) presence + dup bitmaps, key cache — 1 point/thread (best measured)
__global__ void k_build(const int4* __restrict__ coords, int n) {
    int i = blockIdx.x * blockDim.x + threadIdx.x;
    if (i < NBLOCKS_SCAN) g_scanState[i] = 0ULL;  // consumed only by next launch
    if (i >= n) return;
    int4 c = coords[i];
    unsigned key = ((unsigned)((c.x * SPATIAL + c.y) * SPATIAL + c.z)) * SPATIAL + (unsigned)c.w;
    g_keys[i] = key;
    unsigned bit = 1u << (key & 31);
    unsigned old = atomicOr(&g_bitmap[key >> 5], bit);
    if (old & bit) atomicOr(&g_dup[key >> 5], bit);
}

// ---------------------------------------------------------------------------
// 2) single-pass scan (decoupled lookback) -> packed table + dup-row zeroing.
//    Restores g_bitmap / g_dup to zero for the next replay.
//    PDL: waits for build; releases scatter immediately (scatter's pre-wait
//    section touches only inputs).
__global__ void __launch_bounds__(256) k_scan_fused(float4* __restrict__ out) {
    GDC_LAUNCH();   // let scatter's first wave come up while we run
    GDC_WAIT();     // build's writes must be visible before reading bitmaps

    int blk = blockIdx.x, t = threadIdx.x;
    int gw4 = blk * 256 + t;
    uint4 v  = ((const uint4*)g_bitmap)[gw4];
    uint4 d4 = ((const uint4*)g_dup)[gw4];
    unsigned c0 = __popc(v.x), c1 = __popc(v.y), c2 = __popc(v.z), c3 = __popc(v.w);
    unsigned local = c0 + c1 + c2 + c3;

    // restore zeros (scatter reads only g_packed / g_keys)
    uint4 z4 = make_uint4(0, 0, 0, 0);
    ((uint4*)g_bitmap)[gw4] = z4;
    ((uint4*)g_dup)[gw4] = z4;

    // intra-warp inclusive scan
    unsigned inc = local;
#pragma unroll
    for (int o = 1; o < 32; o <<= 1) {
        unsigned nv = __shfl_up_sync(0xffffffffu, inc, o);
        if ((t & 31) >= o) inc += nv;
    }
    __shared__ unsigned ws[8];
    __shared__ unsigned sh_total, sh_excl;
    if ((t & 31) == 31) ws[t >> 5] = inc;
    __syncthreads();
    if (t < 8) {
        unsigned x = ws[t], xi = x;
#pragma unroll
        for (int o = 1; o < 8; o <<= 1) {
            unsigned nv = __shfl_up_sync(0xffu, xi, o);
            if (t >= o) xi += nv;
        }
        ws[t] = xi - x;
        if (t == 7) sh_total = xi;
    }
    __syncthreads();
    unsigned blockTotal = sh_total;

    // publish partial, then decoupled lookback (warp 0)
    if (t == 0)
        atomicExch(&g_scanState[blk], ((unsigned long long)blockTotal << 32) | 1ULL);
    if (t < 32) {
        unsigned excl = 0;
        int idx = blk - 1;
        while (idx >= 0) {
            int look = idx - t;
            unsigned long long s;
            unsigned flag;
            do {
                s = (look >= 0) ? *(volatile unsigned long long*)&g_scanState[look]
                                : 3ULL;
                flag = (unsigned)s;
            } while (__any_sync(0xffffffffu, flag == 0));
            unsigned val = (unsigned)(s >> 32);
            unsigned inclMask = __ballot_sync(0xffffffffu, look >= 0 && flag == 2);
            unsigned contrib;
            if (inclMask) {
                int fi = __ffs(inclMask) - 1;
                contrib = (t <= (unsigned)fi && look >= 0) ? val : 0;
            } else {
                contrib = (look >= 0) ? val : 0;
            }
#pragma unroll
            for (int o = 16; o; o >>= 1) contrib += __shfl_down_sync(0xffffffffu, contrib, o);
            excl += __shfl_sync(0xffffffffu, contrib, 0);
            if (inclMask) break;
            idx -= 32;
        }
        if (t == 0) {
            atomicExch(&g_scanState[blk],
                       ((unsigned long long)(excl + blockTotal) << 32) | 2ULL);
            sh_excl = excl;
            if (blk == NBLOCKS_SCAN - 1) g_numUnique = excl + blockTotal;
        }
    }
    __syncthreads();

    unsigned base = sh_excl + ws[t >> 5] + (inc - local);
    unsigned pw[4] = {v.x, v.y, v.z, v.w};
    unsigned dw[4] = {d4.x, d4.y, d4.z, d4.w};
    unsigned bw[4];
    bw[0] = base;
    bw[1] = base + c0;
    bw[2] = bw[1] + c1;
    bw[3] = bw[2] + c2;
    float4 z = make_float4(0.f, 0.f, 0.f, 0.f);
#pragma unroll
    for (int k = 0; k < 4; k++) {
        g_packed[gw4 * 4 + k] = make_uint4(pw[k], dw[k], bw[k], 0u);
        unsigned d = dw[k];
        while (d) {
            int b = __ffs(d) - 1;
            d &= d - 1;
            unsigned rank = bw[k] + __popc(pw[k] & ((1u << b) - 1u));
            float4* dst = out + (size_t)rank * 8;
#pragma unroll
            for (int q = 0; q < 8; q++) dst[q] = z;
        }
    }
}

// ---------------------------------------------------------------------------
// 3) scatter: 4 threads/point, 2 float4 each; packed-table lookup; pad zero.
//    PDL: feat loads (pure input) issue BEFORE the wait and overlap with scan.
__global__ void k_scatter(const float4* __restrict__ feat,
                          float4* __restrict__ out, int n) {
    int tid = blockIdx.x * blockDim.x + threadIdx.x;
    int p = tid >> 2;    // point index
    int sub = tid & 3;   // handles quarter-rows sub and sub+4
    float4 f0, f1;
    if (p < n) {
        f0 = feat[p * 8 + sub];       // independent of build/scan — prefetch
        f1 = feat[p * 8 + sub + 4];
    }
    GDC_WAIT();                       // scan (and transitively build) complete
    if (p >= n) return;

    int lane = threadIdx.x & 31;
    unsigned info = 0;
    if (sub == 0) {
        unsigned key = g_keys[p];
        uint4 pk = g_packed[key >> 5];      // single 16B L2 lookup
        unsigned b = key & 31;
        unsigned rank = pk.z + __popc(pk.x & ((1u << b) - 1u));
        unsigned isdup = (pk.y >> b) & 1u;
        info = rank | (isdup << 31);
    }
    info = __shfl_sync(0xffffffffu, info, lane & ~3);
    unsigned rank = info & 0x7fffffffu;
    float4* dst = out + (size_t)rank * 8;
    if (info >> 31) {
        asm volatile("red.global.add.v4.f32 [%0], {%1,%2,%3,%4};"
                     :: "l"((float*)(dst + sub)), "f"(f0.x), "f"(f0.y), "f"(f0.z), "f"(f0.w)
                     : "memory");
        asm volatile("red.global.add.v4.f32 [%0], {%1,%2,%3,%4};"
                     :: "l"((float*)(dst + sub + 4)), "f"(f1.x), "f"(f1.y), "f"(f1.z), "f"(f1.w)
                     : "memory");
    } else {
        dst[sub] = f0;
        dst[sub + 4] = f1;
    }

    // padding rows [numUnique, n): never touched by scatter, safe to zero here
    unsigned nu = g_numUnique;
    unsigned row = nu + (unsigned)p;
    if (row < (unsigned)n) {
        float4 z = make_float4(0.f, 0.f, 0.f, 0.f);
        out[(size_t)row * 8 + sub] = z;
        out[(size_t)row * 8 + sub + 4] = z;
    }
}

// ---------------------------------------------------------------------------
extern "C" void kernel_launch(void* const* d_in, const int* in_sizes, int n_in,
                              void* d_out, int out_size) {
    const int4*   coords = (const int4*)d_in[0];
    const float4* feat   = (const float4*)d_in[1];
    float4*       out    = (float4*)d_out;
    int n = in_sizes[0] / 4;

    // 1) build — plain launch
    k_build<<<(n + 255) / 256, 256>>>(coords, n);

    // 2) scan — programmatic dependent launch (overlaps build's drain)
    {
        cudaLaunchConfig_t cfg = {};
        cfg.gridDim = dim3(NBLOCKS_SCAN, 1, 1);
        cfg.blockDim = dim3(256, 1, 1);
        cudaLaunchAttribute attr[1];
        attr[0].id = cudaLaunchAttributeProgrammaticStreamSerialization;
        attr[0].val.programmaticStreamSerializationAllowed = 1;
        cfg.attrs = attr;
        cfg.numAttrs = 1;
        cudaLaunchKernelEx(&cfg, k_scan_fused, out);
    }

    // 3) scatter — programmatic dependent launch (feat prefetch overlaps scan)
    {
        int total = n * 4;
        cudaLaunchConfig_t cfg = {};
        cfg.gridDim = dim3((total + 255) / 256, 1, 1);
        cfg.blockDim = dim3(256, 1, 1);
        cudaLaunchAttribute attr[1];
        attr[0].id = cudaLaunchAttributeProgrammaticStreamSerialization;
        attr[0].val.programmaticStreamSerializationAllowed = 1;
        cfg.attrs = attr;
        cfg.numAttrs = 1;
        cudaLaunchKernelEx(&cfg, k_scatter, feat, out, n);
    }
}